// round 9
// baseline (speedup 1.0000x reference)
#include <cuda_runtime.h>
#include <math_constants.h>

#define BATCH    8
#define NSHAPE   8192
#define NSKEL    2048

#define NB       256
#define XMIN     (-6.0f)
#define INVSTEP  21.3333333f     /* 256 bins over [-6,6] */

#define QG       256             /* queries per group (4 warps x 64) */
#define G1       (BATCH * NSHAPE / QG)   /* 256 */
#define G2       (BATCH * NSKEL  / QG)   /* 64  */
#define NG       (G1 + G2)               /* 320 */
#define NWPG     4               /* warps per group */

#define NESK     (NSKEL  / 2)    /* 1024 packed entries */
#define NESH     (NSHAPE / 2)    /* 4096 */

#define AW_E     128             /* bound rank window: 128 entries = 256 pts */
#define CH_E     64              /* scan chunk: 64 entries = 128 pts */
#define MAXCH1   16              /* 1024/64 */
#define MAXCH2   64              /* 4096/64 */
#define K3B      (G1 * MAXCH1 + G2 * MAXCH2)  /* 8192 */

// Sorted clouds: per-point float4 (x,y,z,|p|^2) + packed pair entries
// (A=(x0,x1,y0,y1), B=(z0,z1,n0,n1)) + bin CDF. Rewritten every call;
// key/counter state zero-init and self-resetting => graph-replay safe.
__device__ float4 g_q4Sh[BATCH][NSHAPE];
__device__ float4 g_q4Sk[BATCH][NSKEL];
__device__ float4 g_pASh[BATCH][NESH], g_pBSh[BATCH][NESH];
__device__ float4 g_pASk[BATCH][NESK], g_pBSk[BATCH][NESK];
__device__ unsigned int g_cdfSh[BATCH][NB + 1];
__device__ unsigned int g_cdfSk[BATCH][NB + 1];
__device__ unsigned int g_w0[NG * NWPG];  // per-warp window start (entries)
__device__ unsigned int g_w1[NG * NWPG];  // per-warp window end
__device__ unsigned int g_e0[NG];         // union window start
__device__ unsigned int g_nch[NG];        // union chunk count
__device__ unsigned int g_key[NG * QG];   // ~bits(min d2); seeded by bound
__device__ unsigned int g_gc[NG];
__device__ unsigned int g_done;
__device__ float        g_accum;

// ---------------------------------------------------------------------------
__device__ __forceinline__ int xbin(float x) {
    int b = (int)floorf((x - XMIN) * INVSTEP);
    return min(max(b, 0), NB - 1);
}
__device__ __forceinline__ unsigned long long pack2(float v) {
    unsigned long long r;
    asm("mov.b64 %0, {%1,%2};" : "=l"(r) : "f"(v), "f"(v));
    return r;
}
__device__ __forceinline__ unsigned long long fma2(unsigned long long a,
                                                   unsigned long long b,
                                                   unsigned long long c) {
    unsigned long long d;
    asm("fma.rn.f32x2 %0, %1, %2, %3;" : "=l"(d) : "l"(a), "l"(b), "l"(c));
    return d;
}
__device__ __forceinline__ void unpack2(unsigned long long v, float& lo, float& hi) {
    asm("mov.b64 {%0,%1}, %2;" : "=f"(lo), "=f"(hi) : "l"(v));
}
__device__ __forceinline__ float wmaxf(float v) {
#pragma unroll
    for (int o = 16; o > 0; o >>= 1) v = fmaxf(v, __shfl_xor_sync(0xffffffffu, v, o));
    return v;
}
__device__ __forceinline__ float block_reduce_sum(float v) {
    __shared__ float ws[4];
    const int lane = threadIdx.x & 31, wid = threadIdx.x >> 5;
#pragma unroll
    for (int o = 16; o > 0; o >>= 1) v += __shfl_down_sync(0xffffffffu, v, o);
    if (lane == 0) ws[wid] = v;
    __syncthreads();
    if (wid == 0) {
        v = (lane < 4) ? ws[lane] : 0.0f;
#pragma unroll
        for (int o = 2; o > 0; o >>= 1) v += __shfl_down_sync(0xffffffffu, v, o);
    }
    return v;
}

// hot loop over packed entries [0,n) of (sA,sB); 2 queries per thread
__device__ __forceinline__ void scan_entries(
    const float4* __restrict__ sA, const float4* __restrict__ sB, int n,
    unsigned long long cx0, unsigned long long cy0, unsigned long long cz0,
    unsigned long long cx1, unsigned long long cy1, unsigned long long cz1,
    float& m0, float& m1)
{
    const ulonglong2* pA = reinterpret_cast<const ulonglong2*>(sA);
    const ulonglong2* pB = reinterpret_cast<const ulonglong2*>(sB);
#pragma unroll 4
    for (int jj = 0; jj < n; jj++) {
        const ulonglong2 A = pA[jj];   // (x-pair, y-pair)
        const ulonglong2 B = pB[jj];   // (z-pair, n-pair)
        unsigned long long t0 = fma2(cx0, A.x, B.y);
        t0 = fma2(cy0, A.y, t0);
        t0 = fma2(cz0, B.x, t0);
        unsigned long long t1 = fma2(cx1, A.x, B.y);
        t1 = fma2(cy1, A.y, t1);
        t1 = fma2(cz1, B.x, t1);
        float lo, hi;
        unpack2(t0, lo, hi); m0 = fminf(m0, fminf(lo, hi));
        unpack2(t1, lo, hi); m1 = fminf(m1, fminf(lo, hi));
    }
}

// ---------------------------------------------------------------------------
// Prep: deterministic counting sort by x-bin per (array,batch).
// 16 blocks x 1024 threads (32 warps). Two-pass rank (no element staging):
//   pass 1: per-warp bin histograms (deterministic warp->chunk ownership)
//   prefix: wHist -> per-warp base offsets + bin CDF
//   pass 2: identical re-walk recomputes ranks and scatters directly.
// ---------------------------------------------------------------------------
__global__ void __launch_bounds__(1024) prep_kernel(
    const float* __restrict__ shape, const float* __restrict__ skel)
{
    __shared__ unsigned int wHist[32][NB];
    __shared__ unsigned int sScan[NB];
    __shared__ unsigned int sCdf[NB + 1];

    const int tid  = threadIdx.x;
    const int w    = tid >> 5;
    const int lane = tid & 31;
    const bool isShape = (blockIdx.x < 8);
    const int b      = isShape ? blockIdx.x : blockIdx.x - 8;
    const int N      = isShape ? NSHAPE : NSKEL;
    const int stride = isShape ? 6 : 3;
    const float* src = isShape ? shape + (size_t)b * NSHAPE * 6
                               : skel  + (size_t)b * NSKEL * 3;

    for (int i = tid; i < 32 * NB; i += 1024) ((unsigned int*)wHist)[i] = 0;
    __syncthreads();

    const int chunk = N >> 5;                  // per-warp contiguous chunk
    const int iters = chunk >> 5;              // 8 (shape) / 2 (skel)
    const int base  = w * chunk;

    // ---- pass 1: histograms ----
    for (int s = 0; s < iters; s++) {
        const int i = base + s * 32 + lane;
        const int bn = xbin(src[i * stride]);
        const unsigned mask  = __match_any_sync(0xffffffffu, bn);
        const unsigned lower = __popc(mask & ((1u << lane) - 1u));
        if (lower == 0) wHist[w][bn] += __popc(mask);
        __syncwarp();
    }
    __syncthreads();

    // ---- per-bin across-warp prefix + totals ----
    if (tid < NB) {
        unsigned run = 0;
#pragma unroll
        for (int ww = 0; ww < 32; ww++) {
            const unsigned c = wHist[ww][tid];
            wHist[ww][tid] = run;
            run += c;
        }
        sScan[tid] = run;
    }
    __syncthreads();
    for (int off = 1; off < NB; off <<= 1) {   // inclusive Hillis-Steele
        unsigned v = 0;
        if (tid < NB && tid >= off) v = sScan[tid - off];
        __syncthreads();
        if (tid < NB) sScan[tid] += v;
        __syncthreads();
    }
    if (tid < NB) sCdf[tid + 1] = sScan[tid];
    if (tid == 0) sCdf[0] = 0;
    __syncthreads();
    // wHist[w][bn] += sCdf[bn]  => absolute scatter bases
    for (int i = tid; i < 32 * NB; i += 1024)
        ((unsigned int*)wHist)[i] += sCdf[i & (NB - 1)];
    __syncthreads();

    // ---- pass 2: identical re-walk, scatter ----
    float4* q4 = isShape ? g_q4Sh[b] : g_q4Sk[b];
    for (int s = 0; s < iters; s++) {
        const int i = base + s * 32 + lane;
        const float* p = src + i * stride;
        const float x = p[0], y = p[1], z = p[2];
        const int bn = xbin(x);
        const unsigned mask  = __match_any_sync(0xffffffffu, bn);
        const unsigned lower = __popc(mask & ((1u << lane) - 1u));
        const unsigned r = wHist[w][bn] + lower;
        __syncwarp();
        q4[r] = make_float4(x, y, z, fmaf(x, x, fmaf(y, y, z * z)));
        if (lower == 0) wHist[w][bn] = r + __popc(mask);
        __syncwarp();
    }
    unsigned int* gcdf = isShape ? g_cdfSh[b] : g_cdfSk[b];
    if (tid <= NB) gcdf[tid] = sCdf[tid];
    __syncthreads();                           // q4 visible block-wide

    // ---- packed-pair candidate layout ----
    float4* pA = isShape ? g_pASh[b] : g_pASk[b];
    float4* pB = isShape ? g_pBSh[b] : g_pBSk[b];
    for (int e = tid; e < (N >> 1); e += 1024) {
        const float4 p0 = q4[2 * e], p1 = q4[2 * e + 1];
        pA[e] = make_float4(p0.x, p1.x, p0.y, p1.y);
        pB[e] = make_float4(p0.z, p1.z, p0.w, p1.w);
    }
}

// ---------------------------------------------------------------------------
// Bound kernel: one block (128 thr, 4 warps) per query group; each warp owns
// 64 consecutive sorted queries. Dense scan of a 256-pt rank window (uniform
// global LDG broadcast) -> per-query upper bound (seeds keys) -> warp-max
// radius -> per-warp exact window + block-union chunk header.
// ---------------------------------------------------------------------------
__global__ void __launch_bounds__(128) bound_kernel()
{
    __shared__ unsigned int sw0[NWPG], sw1[NWPG];

    const int tid  = threadIdx.x;
    const int w    = tid >> 5;
    const int lane = tid & 31;
    const int gid  = blockIdx.x;
    const bool side1 = (gid < G1);

    const float4 *q4, *pA, *pB;
    const unsigned int* cdf;
    int NE, qbase;
    if (side1) {                     // queries = sorted shape, cand = skel
        const int b = gid >> 5;
        qbase = (gid & 31) * QG;
        q4 = g_q4Sh[b]; pA = g_pASk[b]; pB = g_pBSk[b];
        cdf = g_cdfSk[b]; NE = NESK;
    } else {                         // queries = sorted skel, cand = shape
        const int r = gid - G1;
        const int b = r >> 3;
        qbase = (r & 7) * QG;
        q4 = g_q4Sk[b]; pA = g_pASh[b]; pB = g_pBSh[b];
        cdf = g_cdfSh[b]; NE = NESH;
    }

    const int wq = qbase + w * 64;
    const float4 q0 = q4[wq + lane];
    const float4 q1 = q4[wq + 32 + lane];
    const float wxlo = q4[wq].x;               // sorted: warp extents
    const float wxhi = q4[wq + 63].x;

    // per-warp rank window centered at warp x-mid
    const int c  = (int)cdf[xbin(0.5f * (wxlo + wxhi))];
    const int a0 = min(max((c >> 1) - (AW_E >> 1), 0), NE - AW_E);

    const unsigned long long cx0 = pack2(-2.0f * q0.x), cy0 = pack2(-2.0f * q0.y), cz0 = pack2(-2.0f * q0.z);
    const unsigned long long cx1 = pack2(-2.0f * q1.x), cy1 = pack2(-2.0f * q1.y), cz1 = pack2(-2.0f * q1.z);
    float m0 = CUDART_INF_F, m1 = CUDART_INF_F;
    scan_entries(pA + a0, pB + a0, AW_E, cx0, cy0, cz0, cx1, cy1, cz1, m0, m1);

    const float d2_0 = fmaxf(q0.w + m0, 0.0f);
    const float d2_1 = fmaxf(q1.w + m1, 0.0f);

    // seed keys (plain stores: bound completes before scan launch)
    g_key[gid * QG + w * 64 + lane]      = 0xFFFFFFFFu ^ __float_as_uint(d2_0);
    g_key[gid * QG + w * 64 + 32 + lane] = 0xFFFFFFFFu ^ __float_as_uint(d2_1);

    const float rad   = fmaxf(sqrtf(d2_0), sqrtf(d2_1)) * 1.0001f;
    const float rmaxw = wmaxf(rad);

    if (lane == 0) {
        const int p0 = (int)cdf[xbin(wxlo - rmaxw)];
        const int p1 = (int)cdf[xbin(wxhi + rmaxw) + 1];
        const unsigned e0w = (unsigned)(p0 >> 1);
        const unsigned e1w = (unsigned)min((p1 + 1) >> 1, NE);
        g_w0[gid * NWPG + w] = e0w;
        g_w1[gid * NWPG + w] = e1w;
        sw0[w] = e0w; sw1[w] = e1w;
    }
    __syncthreads();
    if (tid == 0) {
        const unsigned mine0 = min(min(sw0[0], sw0[1]), min(sw0[2], sw0[3]));
        const unsigned maxe1 = max(max(sw1[0], sw1[1]), max(sw1[2], sw1[3]));
        g_e0[gid]  = mine0;
        g_nch[gid] = max(1u, (maxe1 - mine0 + CH_E - 1) / CH_E);
    }
}

// ---------------------------------------------------------------------------
// Scan kernel: block = (group, chunk); early-exit when chunk >= nch.
// Tile = CH_E entries of the union window in smem; each warp scans only its
// own window's intersection with the chunk (warp-uniform loop bounds).
// ---------------------------------------------------------------------------
__global__ void __launch_bounds__(128) scan_kernel(float* __restrict__ out)
{
    __shared__ float4 sA[CH_E];
    __shared__ float4 sB[CH_E];
    __shared__ unsigned int sLast;

    const int tid  = threadIdx.x;
    const int w    = tid >> 5;
    const int lane = tid & 31;
    const int bid  = blockIdx.x;

    int gid, ch;
    const float4 *q4, *pA, *pB;
    int NE, qbase;
    if (bid < G1 * MAXCH1) {
        gid = bid >> 4; ch = bid & 15;
        const int b = gid >> 5;
        qbase = (gid & 31) * QG;
        q4 = g_q4Sh[b]; pA = g_pASk[b]; pB = g_pBSk[b]; NE = NESK;
    } else {
        const int t = bid - G1 * MAXCH1;
        const int r = t >> 6; ch = t & 63;
        gid = G1 + r;
        const int b = r >> 3;
        qbase = (r & 7) * QG;
        q4 = g_q4Sk[b]; pA = g_pASh[b]; pB = g_pBSh[b]; NE = NESH;
    }

    const int nch = (int)g_nch[gid];
    if (ch >= nch) return;
    const int e0 = (int)g_e0[gid];

    const int js = e0 + ch * CH_E;
    const int je = min(js + CH_E, NE);
    const int n  = je - js;

    // tile load: threads 0..63 -> A, 64..127 -> B
    if (tid < CH_E) { if (tid < n) sA[tid] = pA[js + tid]; }
    else            { const int i = tid - CH_E; if (i < n) sB[i] = pB[js + i]; }

    const float4 q0 = q4[qbase + w * 64 + lane];
    const float4 q1 = q4[qbase + w * 64 + 32 + lane];
    const unsigned long long cx0 = pack2(-2.0f * q0.x), cy0 = pack2(-2.0f * q0.y), cz0 = pack2(-2.0f * q0.z);
    const unsigned long long cx1 = pack2(-2.0f * q1.x), cy1 = pack2(-2.0f * q1.y), cz1 = pack2(-2.0f * q1.z);

    const int e0w = (int)g_w0[gid * NWPG + w];
    const int e1w = (int)g_w1[gid * NWPG + w];
    const int l0  = max(e0w, js);
    const int l1  = min(e1w, je);
    __syncthreads();

    float m0 = CUDART_INF_F, m1 = CUDART_INF_F;
    if (l0 < l1)
        scan_entries(sA + (l0 - js), sB + (l0 - js), l1 - l0,
                     cx0, cy0, cz0, cx1, cy1, cz1, m0, m1);

    const float d2_0 = fmaxf(q0.w + m0, 0.0f);
    const float d2_1 = fmaxf(q1.w + m1, 0.0f);
    atomicMax(&g_key[gid * QG + w * 64 + lane],      0xFFFFFFFFu ^ __float_as_uint(d2_0));
    atomicMax(&g_key[gid * QG + w * 64 + 32 + lane], 0xFFFFFFFFu ^ __float_as_uint(d2_1));

    // group completion
    __threadfence();
    __syncthreads();
    if (tid == 0) sLast = (atomicAdd(&g_gc[gid], 1u) == (unsigned)(nch - 1));
    __syncthreads();
    if (!sLast) return;
    __threadfence();

    // finalize: read+reset keys, sqrt, sum
    const unsigned int k0 = atomicExch(&g_key[gid * QG + tid], 0u);
    const unsigned int k1 = atomicExch(&g_key[gid * QG + tid + 128], 0u);
    float s = sqrtf(__uint_as_float(0xFFFFFFFFu ^ k0))
            + sqrtf(__uint_as_float(0xFFFFFFFFu ^ k1));
    s = block_reduce_sum(s);

    if (tid == 0) {
        g_gc[gid] = 0;
        atomicAdd(&g_accum, s);
        __threadfence();
        if (atomicAdd(&g_done, 1u) == NG - 1) {
            out[0] = atomicExch(&g_accum, 0.0f) * 1.0e-4f;
            g_done = 0;
        }
    }
}

// ---------------------------------------------------------------------------
extern "C" void kernel_launch(void* const* d_in, const int* in_sizes, int n_in,
                              void* d_out, int out_size)
{
    const float* shape = (const float*)d_in[0];  // (8, 8192, 6) fp32
    const float* skel  = (const float*)d_in[1];  // (8, 2048, 3) fp32
    prep_kernel<<<16, 1024>>>(shape, skel);
    bound_kernel<<<NG, 128>>>();
    scan_kernel<<<K3B, 128>>>((float*)d_out);
}

// round 12
// speedup vs baseline: 1.4462x; 1.4462x over previous
#include <cuda_runtime.h>
#include <math_constants.h>

#define BATCH    8
#define NSHAPE   8192
#define NSKEL    2048
#define SSTRIDE  6
#define TILE     256            // tile points per block
#define NJJ      (TILE / 2)     // 128 packed point-pair entries
#define NQ       8              // queries per thread
#define BLK      128
#define QG       (BLK * NQ)     // 1024 queries per group

#define S1_GROUPS 64            // 8*8192/1024
#define S1_CHUNKS 8             // 2048/256
#define S2_GROUPS 16            // 8*2048/1024
#define S2_CHUNKS 32            // 8192/256
#define S1_BLOCKS (S1_GROUPS * S1_CHUNKS)            // 512
#define NBLOCKS   (S1_BLOCKS + S2_GROUPS * S2_CHUNKS) // 1024
#define NGROUPS   (S1_GROUPS + S2_GROUPS)            // 80
#define NKEYS     (NGROUPS * QG)                     // 81920

// All state zero-initialized at module load and RESTORED to zero by the kernel
// itself each call => single launch, deterministic graph replays, no allocs.
// Min-d2 stored as key = ~bits(d2) (monotone-decreasing since bits(d2) in
// [0,0x7F800000]) => atomicMax(key) == min(d2), and key==0 is the identity.
__device__ unsigned int g_key[NKEYS];
__device__ unsigned int g_gc[NGROUPS];
__device__ unsigned int g_done;
__device__ float        g_accum;

// ---------------------------------------------------------------------------
// packed f32x2 helpers (ptxas never auto-fuses FFMA2 from C++)
// ---------------------------------------------------------------------------
__device__ __forceinline__ unsigned long long pack2(float v) {
    unsigned long long r;
    asm("mov.b64 %0, {%1,%2};" : "=l"(r) : "f"(v), "f"(v));
    return r;
}
__device__ __forceinline__ unsigned long long fma2(unsigned long long a,
                                                   unsigned long long b,
                                                   unsigned long long c) {
    unsigned long long d;
    asm("fma.rn.f32x2 %0, %1, %2, %3;" : "=l"(d) : "l"(a), "l"(b), "l"(c));
    return d;
}
__device__ __forceinline__ void unpack2(unsigned long long v, float& lo, float& hi) {
    asm("mov.b64 {%0,%1}, %2;" : "=f"(lo), "=f"(hi) : "l"(v));
}

__device__ __forceinline__ float block_reduce_sum(float v) {
    __shared__ float warpsum[BLK / 32];
    const int lane = threadIdx.x & 31;
    const int wid  = threadIdx.x >> 5;
#pragma unroll
    for (int o = 16; o > 0; o >>= 1) v += __shfl_down_sync(0xffffffffu, v, o);
    if (lane == 0) warpsum[wid] = v;
    __syncthreads();
    if (wid == 0) {
        v = (lane < (BLK / 32)) ? warpsum[lane] : 0.0f;
#pragma unroll
        for (int o = 2; o > 0; o >>= 1) v += __shfl_down_sync(0xffffffffu, v, o);
    }
    return v;
}

// ---------------------------------------------------------------------------
// Single fused kernel. 1024 blocks of 128 threads (4 warps), 8 queries/thread.
//   blocks [0,512):    side1 — queries = shape pts, tile = 256-pt skel chunk
//   blocks [512,1024): side2 — queries = skel pts,  tile = 256-pt shape chunk
// Tile entry jj packs points j0=2jj, j1=2jj+1:
//   sA[jj]=(x0,x1,y0,y1)  sB[jj]=(z0,z1,n0,n1), n=|p|^2
// Inner loop per jj: 2 LDS.128 + 24 FFMA2 + 16 FMNMX for 16 pairs — the two
// LDS results feed 8 independent query chains, hiding the LDS latency.
// t_j = n_j - 2 q.p_j ; d2 = max(|q|^2 + min_j t_j, 0); merged via atomicMax.
// ---------------------------------------------------------------------------
__global__ void __launch_bounds__(BLK, 4) chamfer_kernel(
    const float* __restrict__ shape, const float* __restrict__ skel,
    float* __restrict__ out)
{
    __shared__ float4 sA[NJJ];
    __shared__ float4 sB[NJJ];
    __shared__ unsigned int sLast;

    const int tid = threadIdx.x;
    const int bid = blockIdx.x;
    const bool side1 = (bid < S1_BLOCKS);

    int gidx, keybase, need;
    float qxv[NQ], qyv[NQ], qzv[NQ];

    if (side1) {
        const int grp   = bid >> 3;           // 0..63
        const int chunk = bid & 7;            // 0..7
        const int b     = grp >> 3;           // 8 groups per batch
        gidx    = grp;
        keybase = grp * QG;
        need    = S1_CHUNKS;

        // tile: skel[b] points [chunk*256, chunk*256+256)
        const float* tb = skel + ((size_t)b * NSKEL + chunk * TILE) * 3;
        {
            const float* s0 = tb + tid * 6;
            const float x0 = s0[0], y0 = s0[1], z0 = s0[2];
            const float x1 = s0[3], y1 = s0[4], z1 = s0[5];
            sA[tid] = make_float4(x0, x1, y0, y1);
            sB[tid] = make_float4(z0, z1,
                                  fmaf(x0, x0, fmaf(y0, y0, z0 * z0)),
                                  fmaf(x1, x1, fmaf(y1, y1, z1 * z1)));
        }
        // queries: shape[b] rows (grp%8)*1024 + tid + 128u
        const float* qb = shape + ((size_t)b * NSHAPE + (grp & 7) * QG + tid) * SSTRIDE;
#pragma unroll
        for (int u = 0; u < NQ; u++) {
            const float* p = qb + u * BLK * SSTRIDE;
            qxv[u] = p[0]; qyv[u] = p[1]; qzv[u] = p[2];
        }
    } else {
        const int r     = bid - S1_BLOCKS;
        const int grp   = r >> 5;             // 0..15
        const int chunk = r & 31;             // 0..31
        const int b     = grp >> 1;           // 2 groups per batch
        gidx    = S1_GROUPS + grp;
        keybase = (S1_GROUPS + grp) * QG;
        need    = S2_CHUNKS;

        // tile: shape[b] points [chunk*256, chunk*256+256) (row stride 6)
        const float* tb = shape + ((size_t)b * NSHAPE + chunk * TILE) * SSTRIDE;
        {
            const float* s0 = tb + tid * 2 * SSTRIDE;
            const float x0 = s0[0], y0 = s0[1], z0 = s0[2];
            const float x1 = s0[6], y1 = s0[7], z1 = s0[8];
            sA[tid] = make_float4(x0, x1, y0, y1);
            sB[tid] = make_float4(z0, z1,
                                  fmaf(x0, x0, fmaf(y0, y0, z0 * z0)),
                                  fmaf(x1, x1, fmaf(y1, y1, z1 * z1)));
        }
        // queries: skel[b] rows (grp%2)*1024 + tid + 128u
        const float* qb = skel + ((size_t)b * NSKEL + (grp & 1) * QG + tid) * 3;
#pragma unroll
        for (int u = 0; u < NQ; u++) {
            const float* p = qb + u * BLK * 3;
            qxv[u] = p[0]; qyv[u] = p[1]; qzv[u] = p[2];
        }
    }
    __syncthreads();

    float pp[NQ];
    unsigned long long cx[NQ], cy[NQ], cz[NQ];
#pragma unroll
    for (int u = 0; u < NQ; u++) {
        pp[u] = fmaf(qxv[u], qxv[u], fmaf(qyv[u], qyv[u], qzv[u] * qzv[u]));
        cx[u] = pack2(-2.0f * qxv[u]);
        cy[u] = pack2(-2.0f * qyv[u]);
        cz[u] = pack2(-2.0f * qzv[u]);
    }

    // ---- hot loop: 128 iters, 16 pairs each ----
    const ulonglong2* pA = reinterpret_cast<const ulonglong2*>(sA);
    const ulonglong2* pB = reinterpret_cast<const ulonglong2*>(sB);
    float mlo[NQ], mhi[NQ];
#pragma unroll
    for (int u = 0; u < NQ; u++) { mlo[u] = CUDART_INF_F; mhi[u] = CUDART_INF_F; }

#pragma unroll 2
    for (int jj = 0; jj < NJJ; jj++) {
        const ulonglong2 A = pA[jj];   // (x-pair, y-pair)
        const ulonglong2 B = pB[jj];   // (z-pair, n-pair)
#pragma unroll
        for (int u = 0; u < NQ; u++) {
            unsigned long long t = fma2(cx[u], A.x, B.y);
            t = fma2(cy[u], A.y, t);
            t = fma2(cz[u], B.x, t);
            float lo, hi;
            unpack2(t, lo, hi);
            mlo[u] = fminf(mlo[u], lo);
            mhi[u] = fminf(mhi[u], hi);
        }
    }

    // ---- merge partial minima (key = ~bits, atomicMax, zero-identity) ----
#pragma unroll
    for (int u = 0; u < NQ; u++) {
        const float d2 = fmaxf(pp[u] + fminf(mlo[u], mhi[u]), 0.0f);
        atomicMax(&g_key[keybase + tid + u * BLK],
                  0xFFFFFFFFu ^ __float_as_uint(d2));
    }

    // ---- group completion: last chunk-block finalizes this query group ----
    __threadfence();
    __syncthreads();
    if (tid == 0) sLast = (atomicAdd(&g_gc[gidx], 1u) == (unsigned)(need - 1));
    __syncthreads();
    if (!sLast) return;
    __threadfence();

    float s = 0.0f;
#pragma unroll
    for (int u = 0; u < NQ; u++) {
        // atomicExch: L1-bypassing read + reset-to-zero for the next replay
        const unsigned int key = atomicExch(&g_key[keybase + tid + u * BLK], 0u);
        s += sqrtf(__uint_as_float(0xFFFFFFFFu ^ key));
    }
    s = block_reduce_sum(s);

    if (tid == 0) {
        g_gc[gidx] = 0;                       // reset own counter
        atomicAdd(&g_accum, s);
        __threadfence();
        if (atomicAdd(&g_done, 1u) == NGROUPS - 1) {
            out[0] = atomicExch(&g_accum, 0.0f) * 1.0e-4f;
            g_done = 0;                       // reset for next replay
        }
    }
}

// ---------------------------------------------------------------------------
extern "C" void kernel_launch(void* const* d_in, const int* in_sizes, int n_in,
                              void* d_out, int out_size)
{
    const float* shape = (const float*)d_in[0];  // (8, 8192, 6) fp32
    const float* skel  = (const float*)d_in[1];  // (8, 2048, 3) fp32
    chamfer_kernel<<<NBLOCKS, BLK>>>(shape, skel, (float*)d_out);
}